// round 3
// baseline (speedup 1.0000x reference)
#include <cuda_runtime.h>
#include <cuda_fp16.h>
#include <cstdint>

#define B_ 256
#define I_ 1152
#define N_ 10
#define D_ 16
#define K_ 8

// u_hat scratch [b][i][n][d] fp16 = 94 MB (fits L2)
__device__ __half g_uhat[(size_t)B_ * I_ * N_ * D_];

// ---------------- helpers ----------------
__device__ __forceinline__ unsigned long long pack2(float a, float b) {
    unsigned long long r;
    asm("mov.b64 %0, {%1, %2};" : "=l"(r) : "f"(a), "f"(b));
    return r;
}
__device__ __forceinline__ unsigned long long fma2(unsigned long long a,
                                                   unsigned long long b,
                                                   unsigned long long c) {
    unsigned long long r;
    asm("fma.rn.f32x2 %0, %1, %2, %3;" : "=l"(r) : "l"(a), "l"(b), "l"(c));
    return r;
}
__device__ __forceinline__ unsigned int cvt2h(unsigned long long v) {
    float lo, hi;
    asm("mov.b64 {%0, %1}, %2;" : "=f"(lo), "=f"(hi) : "l"(v));
    __half2 h = __floats2half2_rn(lo, hi);
    return *reinterpret_cast<unsigned int*>(&h);
}

// ---------------- kernel 1: u_hat = einsum('nidk,bik->bind') fp16 ----------------
__global__ __launch_bounds__(512, 1) void k_uhat(const float* __restrict__ x,
                                                 const float* __restrict__ W) {
    __shared__ unsigned long long sW[8 * 642];
    const int tid = threadIdx.x;
    const int i0 = blockIdx.x * 8;

    for (int idx = tid; idx < 5120; idx += 512) {
        int k    = idx & 7;
        int dp   = (idx >> 3) & 7;
        int n    = (idx >> 6) % 10;
        int iloc = idx / 640;
        const float* wp = W + ((((size_t)n * I_ + i0 + iloc) * D_ + dp * 2) * K_ + k);
        sW[iloc * 642 + n * 64 + dp * 8 + k] = pack2(wp[0], wp[K_]);
    }
    __syncthreads();

    const int iloc = tid & 7;
    const int b0   = tid >> 3;

    float xr[4][8];
#pragma unroll
    for (int j = 0; j < 4; j++) {
        const float4* xp = (const float4*)(x + ((size_t)(b0 + 64 * j) * I_ + i0 + iloc) * K_);
        float4 a = xp[0], c = xp[1];
        xr[j][0] = a.x; xr[j][1] = a.y; xr[j][2] = a.z; xr[j][3] = a.w;
        xr[j][4] = c.x; xr[j][5] = c.y; xr[j][6] = c.z; xr[j][7] = c.w;
    }

    const unsigned long long* wrow = sW + iloc * 642;
#pragma unroll 1
    for (int n = 0; n < 10; n++) {
        unsigned long long acc[4][8];
#pragma unroll
        for (int j = 0; j < 4; j++)
#pragma unroll
            for (int dp = 0; dp < 8; dp++) acc[j][dp] = 0ull;

#pragma unroll
        for (int k = 0; k < 8; k++) {
            unsigned long long xx0 = pack2(xr[0][k], xr[0][k]);
            unsigned long long xx1 = pack2(xr[1][k], xr[1][k]);
            unsigned long long xx2 = pack2(xr[2][k], xr[2][k]);
            unsigned long long xx3 = pack2(xr[3][k], xr[3][k]);
#pragma unroll
            for (int dp = 0; dp < 8; dp++) {
                unsigned long long w2 = wrow[n * 64 + dp * 8 + k];
                acc[0][dp] = fma2(w2, xx0, acc[0][dp]);
                acc[1][dp] = fma2(w2, xx1, acc[1][dp]);
                acc[2][dp] = fma2(w2, xx2, acc[2][dp]);
                acc[3][dp] = fma2(w2, xx3, acc[3][dp]);
            }
        }
#pragma unroll
        for (int j = 0; j < 4; j++) {
            unsigned int r[8];
#pragma unroll
            for (int dp = 0; dp < 8; dp++) r[dp] = cvt2h(acc[j][dp]);
            uint4* op = (uint4*)(g_uhat +
                (((size_t)(b0 + 64 * j) * I_ + i0 + iloc) * N_ + n) * D_);
            op[0] = make_uint4(r[0], r[1], r[2], r[3]);
            op[1] = make_uint4(r[4], r[5], r[6], r[7]);
        }
    }
}

// ---------------- kernel 2: fully fused routing (3 iterations, 2-CTA cluster/b) ----
#define RT_THREADS 384
#define HALF_I 576
#define NSTRIDE 4616                 // u32 stride per n-block (576*8 + 8 pad)
#define U_WORDS (N_ * NSTRIDE)       // 46160
#define SPART_STRIDE 168
#define SMEM_WORDS (U_WORDS + 12 * SPART_STRIDE + 2 * 160 + 160 + 160)
#define SMEM_BYTES (SMEM_WORDS * 4)  // 195,264 B

__global__ __launch_bounds__(RT_THREADS, 1) __cluster_dims__(2, 1, 1)
void k_route_all(float* __restrict__ out) {
    extern __shared__ unsigned int smem[];
    float* smf = (float*)smem;
    const int tid = threadIdx.x;
    const int b = blockIdx.x >> 1;
    unsigned int rank;
    asm("mov.u32 %0, %%cluster_ctarank;" : "=r"(rank));

    // ---- load u half (b, rank) from global, transpose [i][n][d] -> [n][i][d]
    const uint4* gsrc = (const uint4*)(g_uhat +
        ((size_t)b * I_ + (int)rank * HALF_I) * N_ * D_);
    for (int t = tid; t < 11520; t += RT_THREADS) {
        uint4 v = gsrc[t];
        int iloc = t / 20;
        int rem  = t - iloc * 20;
        int n = rem >> 1, dh = rem & 1;
        *(uint4*)&smem[n * NSTRIDE + iloc * 8 + dh * 4] = v;
    }

    const int w = tid >> 5, lane = tid & 31;
    const int il = lane >> 2, dq = lane & 3;
    const int base0 = w * 64 + il * 8 + dq * 2;

    float* sPart = smf + U_WORDS;                // [12][168]
    float* ssum  = sPart + 12 * SPART_STRIDE;    // [2][160] ping-pong
    float* stot  = ssum + 2 * 160;               // [160]
    float* ocum  = stot + 160;                   // [160]

    unsigned int ssum_sa = (unsigned int)__cvta_generic_to_shared(ssum);
    unsigned int peer_ssum;
    asm("mapa.shared::cluster.u32 %0, %1, %2;"
        : "=r"(peer_ssum) : "r"(ssum_sa), "r"(rank ^ 1u));

    __syncthreads();

#pragma unroll 1
    for (int r = 0; r < 3; r++) {
        const int buf = r & 1;
        float sp[N_][4];
#pragma unroll
        for (int n = 0; n < N_; n++)
#pragma unroll
            for (int q = 0; q < 4; q++) sp[n][q] = 0.0f;

#pragma unroll 1
        for (int round = 0; round < 6; round++) {
            const int abase = round * 768 + base0;
            float4 fv[N_];
#pragma unroll
            for (int n = 0; n < N_; n++) {
                uint2 v = *(const uint2*)&smem[n * NSTRIDE + abase];
                float2 f0 = __half22float2(*(const __half2*)&v.x);
                float2 f1 = __half22float2(*(const __half2*)&v.y);
                fv[n] = make_float4(f0.x, f0.y, f1.x, f1.y);
            }
            float c[N_];
            if (r == 0) {
#pragma unroll
                for (int n = 0; n < N_; n++) c[n] = 0.1f;
            } else {
                float part[N_];
#pragma unroll
                for (int n = 0; n < N_; n++) {
                    const float* o = &ocum[n * 16 + dq * 4];
                    part[n] = fv[n].x * o[0] + fv[n].y * o[1] +
                              fv[n].z * o[2] + fv[n].w * o[3];
                }
#pragma unroll
                for (int n = 0; n < N_; n++) {
                    part[n] += __shfl_xor_sync(0xffffffffu, part[n], 1);
                    part[n] += __shfl_xor_sync(0xffffffffu, part[n], 2);
                }
                float m = part[0];
#pragma unroll
                for (int n = 1; n < N_; n++) m = fmaxf(m, part[n]);
                float sum = 0.0f;
#pragma unroll
                for (int n = 0; n < N_; n++) { c[n] = __expf(part[n] - m); sum += c[n]; }
                float inv = __fdividef(1.0f, sum);
#pragma unroll
                for (int n = 0; n < N_; n++) c[n] *= inv;
            }
#pragma unroll
            for (int n = 0; n < N_; n++) {
                sp[n][0] += c[n] * fv[n].x;
                sp[n][1] += c[n] * fv[n].y;
                sp[n][2] += c[n] * fv[n].z;
                sp[n][3] += c[n] * fv[n].w;
            }
        }

        // reduce sp over il lanes (bits 2..4)
#pragma unroll
        for (int ofs = 4; ofs <= 16; ofs <<= 1)
#pragma unroll
            for (int n = 0; n < N_; n++)
#pragma unroll
                for (int q = 0; q < 4; q++)
                    sp[n][q] += __shfl_xor_sync(0xffffffffu, sp[n][q], ofs);

        if (il == 0) {
#pragma unroll
            for (int n = 0; n < N_; n++)
                *(float4*)&sPart[w * SPART_STRIDE + n * 16 + dq * 4] =
                    make_float4(sp[n][0], sp[n][1], sp[n][2], sp[n][3]);
        }
        __syncthreads();

        if (tid < 160) {
            float s = 0.0f;
#pragma unroll
            for (int ww = 0; ww < 12; ww++) s += sPart[ww * SPART_STRIDE + tid];
            ssum[buf * 160 + tid] = s;
        }
        // cluster-wide barrier: ssum visible to peer
        asm volatile("barrier.cluster.arrive.aligned;" ::: "memory");
        asm volatile("barrier.cluster.wait.aligned;" ::: "memory");

        if (tid < 160) {
            float pv;
            unsigned int pa = peer_ssum + (unsigned int)(buf * 160 + tid) * 4u;
            asm volatile("ld.shared::cluster.f32 %0, [%1];" : "=f"(pv) : "r"(pa));
            stot[tid] = ssum[buf * 160 + tid] + pv;
        }
        __syncthreads();

        if (tid < 160) {
            const int n = tid >> 4;
            float ns = 0.0f;
#pragma unroll
            for (int j = 0; j < 16; j++) {
                float t = stot[n * 16 + j];
                ns += t * t;
            }
            float f = sqrtf(ns) / (1.0f + ns);
            float val = stot[tid] * f;
            if (r < 2) ocum[tid] = (r == 0) ? val : ocum[tid] + val;
            else if (rank == 0) out[b * 160 + tid] = val;
        }
        __syncthreads();
    }
    // do not exit while peer may still read our ssum
    asm volatile("barrier.cluster.arrive.aligned;" ::: "memory");
    asm volatile("barrier.cluster.wait.aligned;" ::: "memory");
}

// ---------------- launch ----------------
extern "C" void kernel_launch(void* const* d_in, const int* in_sizes, int n_in,
                              void* d_out, int out_size) {
    const float* x = (const float*)d_in[0];   // inputs [B, I, Din]
    const float* W = (const float*)d_in[1];   // W      [N, I, D, Din]
    if (n_in >= 2 && in_sizes[0] == N_ * I_ * D_ * K_) {
        const float* t = x; x = W; W = t;
    }
    float* out = (float*)d_out;

    cudaFuncSetAttribute(k_route_all,
                         cudaFuncAttributeMaxDynamicSharedMemorySize, SMEM_BYTES);

    k_uhat<<<I_ / 8, 512>>>(x, W);
    k_route_all<<<2 * B_, RT_THREADS, SMEM_BYTES>>>(out);
}